// round 7
// baseline (speedup 1.0000x reference)
#include <cuda_runtime.h>
#include <cstdint>
#include <cstdio>

#define S_LEN 2048
#define HDIM  128
#define NBATCH 32
#define BM 64            // q rows per CTA
#define BN 64            // kv rows per iteration
#define THREADS 128
#define PAD 136          // Q/K smem row stride (words); 136 % 32 == 8
#define PADT 72          // V^T smem row stride (words); 72 % 32 == 8
#define MPAD 68          // mask smem row stride (words)
#define MWORDS (BN * MPAD)   // words per mask buffer (64 rows x 68)
#define KV_TILES (S_LEN / BN)
#define QCH (HDIM / 8)   // 16 k-chunks for QK^T
#define LOG2E 1.4426950408889634f
#define QSCALE 0.12751743f   // log2(e)/sqrt(128)

// tf32 scratch, converted once by prep kernels:
//  g_q: plain [n][s][d] (pre-scaled)
//  g_k: per-row interleaved: col c*8+o -> word c*8 + (o&3)*2 + (o>>2)
//  g_vt: transposed [n][d][k], k interleaved within 64-blocks:
//        l = ch*8+r -> p = ch*8 + (r&3)*2 + (r>>2)
__device__ unsigned g_q[NBATCH * S_LEN * HDIM];
__device__ unsigned g_k[NBATCH * S_LEN * HDIM];
__device__ unsigned g_vt[NBATCH * S_LEN * HDIM];

__device__ __forceinline__ unsigned cvt_tf32(float x) {
    unsigned r;
    asm("cvt.rna.tf32.f32 %0, %1;" : "=r"(r) : "f"(x));
    return r;
}

__device__ __forceinline__ void mma_tf32(float* d, const unsigned* a, unsigned b0, unsigned b1) {
    asm volatile(
        "mma.sync.aligned.m16n8k8.row.col.f32.tf32.tf32.f32 "
        "{%0,%1,%2,%3}, {%4,%5,%6,%7}, {%8,%9}, {%0,%1,%2,%3};"
        : "+f"(d[0]), "+f"(d[1]), "+f"(d[2]), "+f"(d[3])
        : "r"(a[0]), "r"(a[1]), "r"(a[2]), "r"(a[3]), "r"(b0), "r"(b1));
}

__device__ __forceinline__ void cp_async16(unsigned saddr, const void* gaddr) {
    asm volatile("cp.async.cg.shared.global [%0], [%1], 16;" :: "r"(saddr), "l"(gaddr));
}
__device__ __forceinline__ void cp_commit() {
    asm volatile("cp.async.commit_group;");
}

// Fast 2^x via FFMA polynomial (avoids the MUFU throughput wall).
__device__ __forceinline__ float exp2_fast(float x) {
    x = fmaxf(x, -120.0f);
    float z = x + 12582912.0f;
    int   n = __float_as_int(z) - 0x4B400000;
    float f = x - (z - 12582912.0f);
    float p =            1.3333558146e-3f;
    p = fmaf(p, f,       9.6181291976e-3f);
    p = fmaf(p, f,       5.5504108665e-2f);
    p = fmaf(p, f,       2.4022650696e-1f);
    p = fmaf(p, f,       6.9314718056e-1f);
    p = fmaf(p, f,       1.0f);
    return __int_as_float(__float_as_int(p) + (n << 23));
}

// ---------------- Prep 1: Q (scaled, plain) + K (row-interleaved) ----------------
__global__ void __launch_bounds__(256)
prep_qk_kernel(const float* __restrict__ qkv)
{
    unsigned idx = blockIdx.x * 256 + threadIdx.x;   // float4 slot
    unsigned row = idx >> 5;                         // n*S_LEN + s
    unsigned c4  = (idx & 31) << 2;
    const float* src = qkv + (size_t)row * (3 * HDIM) + c4;
    float4 q4 = *(const float4*)(src);
    float4 k4 = *(const float4*)(src + HDIM);
    uint4 qo;
    qo.x = cvt_tf32(q4.x * QSCALE); qo.y = cvt_tf32(q4.y * QSCALE);
    qo.z = cvt_tf32(q4.z * QSCALE); qo.w = cvt_tf32(q4.w * QSCALE);
    *(uint4*)(g_q + (size_t)row * HDIM + c4) = qo;
    // K interleave: cols c4+j (j=0..3) -> word chunk*8 + 2j + hi
    unsigned* kdst = g_k + (size_t)row * HDIM + (c4 >> 3) * 8 + ((c4 >> 2) & 1);
    kdst[0] = cvt_tf32(k4.x);
    kdst[2] = cvt_tf32(k4.y);
    kdst[4] = cvt_tf32(k4.z);
    kdst[6] = cvt_tf32(k4.w);
}

// ---------------- Prep 2: V -> transposed + k-interleaved tf32 ----------------
#define SPAD 129
__global__ void __launch_bounds__(256)
prep_v_kernel(const float* __restrict__ qkv)
{
    __shared__ unsigned sT[64 * SPAD];
    const int n  = blockIdx.x >> 5;
    const int k0 = (blockIdx.x & 31) * 64;
    const int tid = threadIdx.x;

    // load 64 k-rows x 128 d, convert tf32
    #pragma unroll
    for (int i = 0; i < 8; ++i) {
        int lin = i * 256 + tid;
        int r  = lin >> 5;
        int d4 = (lin & 31) << 2;
        float4 v = *(const float4*)(qkv + ((size_t)(n * S_LEN + k0 + r)) * (3 * HDIM) + 2 * HDIM + d4);
        unsigned* s = sT + r * SPAD + d4;
        s[0] = cvt_tf32(v.x); s[1] = cvt_tf32(v.y);
        s[2] = cvt_tf32(v.z); s[3] = cvt_tf32(v.w);
    }
    __syncthreads();

    // write out: g_vt[n][d][k0 + p], p = 4j..4j+3 ; l(q) = ch*8 + (q&1)*4 + (q>>1)
    #pragma unroll
    for (int i = 0; i < 8; ++i) {
        int lin = i * 256 + tid;
        int d = lin >> 4;
        int j = lin & 15;
        int ch = j >> 1;
        int qb = (j & 1) * 4;    // q = qb..qb+3
        uint4 o;
        o.x = sT[(ch * 8 + ((qb + 0) & 1) * 4 + ((qb + 0) >> 1)) * SPAD + d];
        o.y = sT[(ch * 8 + ((qb + 1) & 1) * 4 + ((qb + 1) >> 1)) * SPAD + d];
        o.z = sT[(ch * 8 + ((qb + 2) & 1) * 4 + ((qb + 2) >> 1)) * SPAD + d];
        o.w = sT[(ch * 8 + ((qb + 3) & 1) * 4 + ((qb + 3) >> 1)) * SPAD + d];
        *(uint4*)(g_vt + ((size_t)(n * HDIM + d)) * S_LEN + k0 + j * 4) = o;
    }
}

extern __shared__ float smem_f[];

__global__ void __launch_bounds__(THREADS, 2)
attn_fa2_tf32_kernel(const float* __restrict__ mask,
                     float* __restrict__ out)
{
    float* sK  = smem_f;                         // BN x PAD (Q plain during prologue; interleaved K after)
    float* sVT = smem_f + BN * PAD;              // HDIM x PADT (transposed interleaved V)
    float* sM  = smem_f + BN * PAD + HDIM * PADT; // 2 x (BN x MPAD) mask double buffer

    const int tid  = threadIdx.x;
    const int lane = tid & 31;
    const int warp = tid >> 5;
    const int g = lane >> 2;   // group id 0..7
    const int t = lane & 3;    // thread-in-group 0..3

    const int n  = blockIdx.y;
    const int q0 = blockIdx.x * BM;

    const float* gm = mask + (size_t)n * S_LEN * S_LEN;
    const unsigned sK_u32  = (unsigned)__cvta_generic_to_shared(sK);
    const unsigned sVT_u32 = (unsigned)__cvta_generic_to_shared(sVT);
    const unsigned sM_u32  = (unsigned)__cvta_generic_to_shared(sM);

    // ---------------- Prologue: cp.async Q tile (group 0), then mask tile 0 (group 1)
    {
        const unsigned* srcQ = g_q + (size_t)(n * S_LEN + q0) * HDIM;
        #pragma unroll
        for (int i = 0; i < 16; ++i) {
            int lin = i * THREADS + tid;
            int r = lin >> 5;
            int c4 = (lin & 31) << 2;
            cp_async16(sK_u32 + (r * PAD + c4) * 4, srcQ + (size_t)r * HDIM + c4);
        }
        cp_commit();
    }
    {
        const int row   = tid >> 4;
        const int col16 = tid & 15;
        const float* src = gm + (size_t)(q0 + row) * S_LEN + col16 * 4;
        unsigned dst = sM_u32 + (row * MPAD + col16 * 4) * 4;
        #pragma unroll
        for (int c = 0; c < 8; ++c) {
            cp_async16(dst + c * (8 * MPAD * 4), src + (size_t)(c * 8) * S_LEN);
        }
        cp_commit();
    }
    asm volatile("cp.async.wait_group 1;");   // Q arrived; mask0 still in flight
    __syncthreads();

    unsigned qA[QCH][4];
    {
        const unsigned* sQ = (const unsigned*)sK;
        const int r0 = warp * 16 + g;
        #pragma unroll
        for (int c = 0; c < QCH; ++c) {
            qA[c][0] = sQ[(size_t)(r0)     * PAD + c * 8 + t];
            qA[c][1] = sQ[(size_t)(r0 + 8) * PAD + c * 8 + t];
            qA[c][2] = sQ[(size_t)(r0)     * PAD + c * 8 + t + 4];
            qA[c][3] = sQ[(size_t)(r0 + 8) * PAD + c * 8 + t + 4];
        }
    }
    __syncthreads();   // all warps done reading Q before K overwrites sK

    // ---------------- Flash-attention state
    float oacc[16][4];
    #pragma unroll
    for (int d = 0; d < 16; ++d) {
        oacc[d][0] = 0.f; oacc[d][1] = 0.f; oacc[d][2] = 0.f; oacc[d][3] = 0.f;
    }
    float m0 = -1e30f, m1 = -1e30f, l0 = 0.f, l1 = 0.f;

    for (int kt = 0; kt < KV_TILES; ++kt) {
        const int k0 = kt * BN;

        // ---- stage K (interleaved rows) and V^T via bare cp.async ----
        {
            const unsigned* srcK = g_k + (size_t)(n * S_LEN + k0) * HDIM;
            #pragma unroll
            for (int i = 0; i < 16; ++i) {
                int lin = i * THREADS + tid;
                int r = lin >> 5;
                int c4 = (lin & 31) << 2;
                cp_async16(sK_u32 + (r * PAD + c4) * 4, srcK + (size_t)r * HDIM + c4);
            }
            const unsigned* srcV = g_vt + (size_t)n * HDIM * S_LEN + k0;
            #pragma unroll
            for (int i = 0; i < 16; ++i) {
                int lin = i * THREADS + tid;
                int d   = lin >> 4;
                int c16 = (lin & 15) << 2;
                cp_async16(sVT_u32 + (d * PADT + c16) * 4, srcV + (size_t)d * S_LEN + c16);
            }
            cp_commit();
        }

        // ---- prefetch next mask tile; wait for KV(kt) + mask(kt) ----
        if (kt + 1 < KV_TILES) {
            const int row   = tid >> 4;
            const int col16 = tid & 15;
            const float* src = gm + (size_t)(q0 + row) * S_LEN + (k0 + BN) + col16 * 4;
            unsigned dst = sM_u32 + (((kt + 1) & 1) * MWORDS + row * MPAD + col16 * 4) * 4;
            #pragma unroll
            for (int c = 0; c < 8; ++c) {
                cp_async16(dst + c * (8 * MPAD * 4), src + (size_t)(c * 8) * S_LEN);
            }
            cp_commit();
            asm volatile("cp.async.wait_group 1;");   // leaves mask(kt+1) in flight
        } else {
            asm volatile("cp.async.wait_group 0;");
        }
        __syncthreads();

        // ---- S = Q K^T + mask*log2e ; mask init from smem
        float sacc[8][4];
        {
            const float* mrow = sM + (kt & 1) * MWORDS + (warp * 16 + g) * MPAD + 2 * t;
            #pragma unroll
            for (int nt = 0; nt < 8; ++nt) {
                float2 a = *(const float2*)(mrow + nt * 8);
                float2 b = *(const float2*)(mrow + 8 * MPAD + nt * 8);
                sacc[nt][0] = a.x * LOG2E; sacc[nt][1] = a.y * LOG2E;
                sacc[nt][2] = b.x * LOG2E; sacc[nt][3] = b.y * LOG2E;
            }
        }
        {
            // K fragments: one conflict-free LDS.64 per MMA (cols c*8+t, c*8+t+4
            // are adjacent words in the interleaved layout)
            const unsigned* sKu = (const unsigned*)sK;
            #pragma unroll
            for (int c = 0; c < QCH; ++c) {
                #pragma unroll
                for (int nt = 0; nt < 8; ++nt) {
                    uint2 kb = *(const uint2*)&sKu[(size_t)(nt * 8 + g) * PAD + c * 8 + 2 * t];
                    mma_tf32(sacc[nt], qA[c], kb.x, kb.y);
                }
            }
        }

        // ---- online softmax (base 2) ----
        float vmax0 = -1e30f, vmax1 = -1e30f;
        #pragma unroll
        for (int nt = 0; nt < 8; ++nt) {
            vmax0 = fmaxf(vmax0, fmaxf(sacc[nt][0], sacc[nt][1]));
            vmax1 = fmaxf(vmax1, fmaxf(sacc[nt][2], sacc[nt][3]));
        }
        vmax0 = fmaxf(vmax0, __shfl_xor_sync(0xffffffffu, vmax0, 1));
        vmax0 = fmaxf(vmax0, __shfl_xor_sync(0xffffffffu, vmax0, 2));
        vmax1 = fmaxf(vmax1, __shfl_xor_sync(0xffffffffu, vmax1, 1));
        vmax1 = fmaxf(vmax1, __shfl_xor_sync(0xffffffffu, vmax1, 2));

        float mn0 = fmaxf(m0, vmax0), mn1 = fmaxf(m1, vmax1);
        float al0 = exp2_fast(m0 - mn0), al1 = exp2_fast(m1 - mn1);
        m0 = mn0; m1 = mn1;

        float rs0 = 0.f, rs1 = 0.f;
        #pragma unroll
        for (int nt = 0; nt < 8; ++nt) {
            sacc[nt][0] = exp2_fast(sacc[nt][0] - mn0);
            sacc[nt][1] = exp2_fast(sacc[nt][1] - mn0);
            sacc[nt][2] = exp2_fast(sacc[nt][2] - mn1);
            sacc[nt][3] = exp2_fast(sacc[nt][3] - mn1);
            rs0 += sacc[nt][0] + sacc[nt][1];
            rs1 += sacc[nt][2] + sacc[nt][3];
        }
        rs0 += __shfl_xor_sync(0xffffffffu, rs0, 1);
        rs0 += __shfl_xor_sync(0xffffffffu, rs0, 2);
        rs1 += __shfl_xor_sync(0xffffffffu, rs1, 1);
        rs1 += __shfl_xor_sync(0xffffffffu, rs1, 2);
        l0 = l0 * al0 + rs0;
        l1 = l1 * al1 + rs1;

        // rescale O only if some row's max actually changed (exp2_fast(0)==1.0f exactly)
        if (!__all_sync(0xffffffffu, (al0 == 1.0f) && (al1 == 1.0f))) {
            #pragma unroll
            for (int d = 0; d < 16; ++d) {
                oacc[d][0] *= al0; oacc[d][1] *= al0;
                oacc[d][2] *= al1; oacc[d][3] *= al1;
            }
        }

        // ---- O += P V : P (C-layout) -> A-fragments via quad shuffles;
        //      V fragments: one conflict-free LDS.64 per MMA (rows ch*8+t, +4
        //      adjacent in the transposed interleaved layout)
        {
            const unsigned* sVu = (const unsigned*)sVT;
            const unsigned srcA = (lane & 28) | (t >> 1);
            const unsigned srcB = srcA + 2;
            const bool odd = t & 1;
            #pragma unroll
            for (int ch = 0; ch < 8; ++ch) {
                float x00 = __shfl_sync(0xffffffffu, sacc[ch][0], srcA);
                float x01 = __shfl_sync(0xffffffffu, sacc[ch][1], srcA);
                float x10 = __shfl_sync(0xffffffffu, sacc[ch][2], srcA);
                float x11 = __shfl_sync(0xffffffffu, sacc[ch][3], srcA);
                float y00 = __shfl_sync(0xffffffffu, sacc[ch][0], srcB);
                float y01 = __shfl_sync(0xffffffffu, sacc[ch][1], srcB);
                float y10 = __shfl_sync(0xffffffffu, sacc[ch][2], srcB);
                float y11 = __shfl_sync(0xffffffffu, sacc[ch][3], srcB);
                unsigned aP[4];
                aP[0] = cvt_tf32(odd ? x01 : x00);  // row g,   col 8ch+t
                aP[1] = cvt_tf32(odd ? x11 : x10);  // row g+8, col 8ch+t
                aP[2] = cvt_tf32(odd ? y01 : y00);  // row g,   col 8ch+t+4
                aP[3] = cvt_tf32(odd ? y11 : y10);  // row g+8, col 8ch+t+4
                #pragma unroll
                for (int dt = 0; dt < 16; ++dt) {
                    uint2 vb = *(const uint2*)&sVu[(size_t)(dt * 8 + g) * PADT + ch * 8 + 2 * t];
                    mma_tf32(oacc[dt], aP, vb.x, vb.y);
                }
            }
        }
        __syncthreads();
    }

    // ---------------- Epilogue
    const float inv0 = 1.0f / l0;
    const float inv1 = 1.0f / l1;
    float* gout = out + ((size_t)n * S_LEN + q0 + warp * 16) * HDIM;
    #pragma unroll
    for (int dt = 0; dt < 16; ++dt) {
        float2 v0 = make_float2(oacc[dt][0] * inv0, oacc[dt][1] * inv0);
        float2 v1 = make_float2(oacc[dt][2] * inv1, oacc[dt][3] * inv1);
        *(float2*)(gout + (size_t)g * HDIM + dt * 8 + 2 * t)       = v0;
        *(float2*)(gout + (size_t)(g + 8) * HDIM + dt * 8 + 2 * t) = v1;
    }
}

extern "C" void kernel_launch(void* const* d_in, const int* in_sizes, int n_in,
                              void* d_out, int out_size)
{
    const float* qkv  = (const float*)d_in[0];
    const float* mask = (const float*)d_in[1];
    float* out = (float*)d_out;

    prep_qk_kernel<<<NBATCH * S_LEN * (HDIM / 4) / 256, 256>>>(qkv);
    prep_v_kernel<<<NBATCH * (S_LEN / 64), 256>>>(qkv);

    const int smem_bytes = (BN * PAD + HDIM * PADT + 2 * MWORDS) * (int)sizeof(float);  // 106496
    cudaFuncSetAttribute(attn_fa2_tf32_kernel,
                         cudaFuncAttributeMaxDynamicSharedMemorySize, smem_bytes);

    dim3 grid(S_LEN / BM, NBATCH);
    attn_fa2_tf32_kernel<<<grid, THREADS, smem_bytes>>>(mask, out);
}